// round 1
// baseline (speedup 1.0000x reference)
#include <cuda_runtime.h>
#include <cstdint>
#include <cstddef>

#define DI __device__ __forceinline__

// Problem shape (fixed for this instance)
constexpr int Bn = 8, Nn = 1024, Dn = 256, Hn = 4;
constexpr int ROWS = Bn * Nn;  // 8192

// -------- scratch (static device globals: allocation-free) --------
__device__ float g_Q[ROWS * Dn];
__device__ float g_K[ROWS * Dn];
__device__ float g_V[ROWS * Dn];
__device__ float g_M[ROWS * Dn];
__device__ float g_S[(size_t)Bn * Hn * Nn * Nn];  // 134 MB score scratch

// -------- packed f32x2 helpers (sm_100+) --------
DI unsigned long long pack2(float lo, float hi) {
    unsigned long long r;
    asm("mov.b64 %0, {%1, %2};" : "=l"(r) : "f"(lo), "f"(hi));
    return r;
}
DI void fma2(unsigned long long& d, unsigned long long a, unsigned long long b) {
    asm("fma.rn.f32x2 %0, %1, %2, %0;" : "+l"(d) : "l"(a), "l"(b));
}
DI float2 unpack2(unsigned long long v) {
    float lo, hi;
    asm("mov.b64 {%0, %1}, %2;" : "=f"(lo), "=f"(hi) : "l"(v));
    return make_float2(lo, hi);
}

// monotone float->uint mapping (order-preserving)
DI unsigned mapf(float x) {
    unsigned b = __float_as_uint(x);
    return (b & 0x80000000u) ? ~b : (b | 0x80000000u);
}
DI float invmap(unsigned u) {
    unsigned b = (u & 0x80000000u) ? (u & 0x7FFFFFFFu) : ~u;
    return __uint_as_float(b);
}

// ============================================================================
// GEMM: C[m,n] = sum_k A[m*256+k] * W[n*256+k] + bias[n]
// M = 8192, N = 256, K = 256. Tiles 64x64x16, 256 thr, 4x4 per thread (f32x2).
// ============================================================================
__global__ void __launch_bounds__(256) gemm256_kernel(
    const float* __restrict__ A, const float* __restrict__ W,
    const float* __restrict__ bias, float* __restrict__ C)
{
    __shared__ __align__(16) float As[16 * 68];
    __shared__ __align__(16) float Bs[16 * 68];

    const int tid  = threadIdx.x;
    const int m0   = blockIdx.y * 64;
    const int n0   = blockIdx.x * 64;
    const int trow = (tid >> 4) << 2;   // 0..60
    const int tcol = (tid & 15) << 2;   // 0..60
    const int lm   = tid >> 2;          // 0..63
    const int lq   = (tid & 3) << 2;    // 0,4,8,12

    unsigned long long acc[4][2];
#pragma unroll
    for (int i = 0; i < 4; ++i) { acc[i][0] = 0ULL; acc[i][1] = 0ULL; }

    const float* Aptr = A + (size_t)(m0 + lm) * 256 + lq;
    const float* Wptr = W + (size_t)(n0 + lm) * 256 + lq;

    for (int kb = 0; kb < 256; kb += 16) {
        float4 av = *(const float4*)(Aptr + kb);
        float4 bv = *(const float4*)(Wptr + kb);
        __syncthreads();
        As[(lq + 0) * 68 + lm] = av.x;
        As[(lq + 1) * 68 + lm] = av.y;
        As[(lq + 2) * 68 + lm] = av.z;
        As[(lq + 3) * 68 + lm] = av.w;
        Bs[(lq + 0) * 68 + lm] = bv.x;
        Bs[(lq + 1) * 68 + lm] = bv.y;
        Bs[(lq + 2) * 68 + lm] = bv.z;
        Bs[(lq + 3) * 68 + lm] = bv.w;
        __syncthreads();
#pragma unroll
        for (int kk = 0; kk < 16; ++kk) {
            float4 a = *(const float4*)&As[kk * 68 + trow];
            ulonglong2 b2 = *(const ulonglong2*)&Bs[kk * 68 + tcol];
            unsigned long long a0 = pack2(a.x, a.x), a1 = pack2(a.y, a.y);
            unsigned long long a2 = pack2(a.z, a.z), a3 = pack2(a.w, a.w);
            fma2(acc[0][0], a0, b2.x); fma2(acc[0][1], a0, b2.y);
            fma2(acc[1][0], a1, b2.x); fma2(acc[1][1], a1, b2.y);
            fma2(acc[2][0], a2, b2.x); fma2(acc[2][1], a2, b2.y);
            fma2(acc[3][0], a3, b2.x); fma2(acc[3][1], a3, b2.y);
        }
    }

#pragma unroll
    for (int i = 0; i < 4; ++i) {
        int m = m0 + trow + i;
#pragma unroll
        for (int p = 0; p < 2; ++p) {
            float2 c = unpack2(acc[i][p]);
            int n = n0 + tcol + p * 2;
            float2 bb = *(const float2*)&bias[n];
            float2 o = make_float2(c.x + bb.x, c.y + bb.y);
            *(float2*)&C[(size_t)m * 256 + n] = o;
        }
    }
}

// ============================================================================
// Scores: S[b,h,i,j] = 0.125 * dot(Q[b,i,h*64:+64], K[b,j,h*64:+64]) - 0.1*td[b,i,j]
// per-CTA 64x64 output tile, full K=64.
// ============================================================================
__global__ void __launch_bounds__(256) scores_kernel(const float* __restrict__ td)
{
    __shared__ __align__(16) float As[64 * 68];
    __shared__ __align__(16) float Bs[64 * 68];

    const int tid  = threadIdx.x;
    const int bh   = blockIdx.z;        // b*4 + h
    const int b    = bh >> 2;
    const int h    = bh & 3;
    const int i0   = blockIdx.y * 64;
    const int j0   = blockIdx.x * 64;
    const int trow = (tid >> 4) << 2;
    const int tcol = (tid & 15) << 2;

    {
        const float* Qb = g_Q + ((size_t)(b * Nn) + i0) * 256 + h * 64;
        const float* Kb = g_K + ((size_t)(b * Nn) + j0) * 256 + h * 64;
#pragma unroll
        for (int r = 0; r < 4; ++r) {
            int id = tid + 256 * r;
            int m  = id >> 4;          // 0..63
            int q  = (id & 15) << 2;   // 0..60
            float4 av = *(const float4*)(Qb + (size_t)m * 256 + q);
            float4 bv = *(const float4*)(Kb + (size_t)m * 256 + q);
            As[(q + 0) * 68 + m] = av.x;
            As[(q + 1) * 68 + m] = av.y;
            As[(q + 2) * 68 + m] = av.z;
            As[(q + 3) * 68 + m] = av.w;
            Bs[(q + 0) * 68 + m] = bv.x;
            Bs[(q + 1) * 68 + m] = bv.y;
            Bs[(q + 2) * 68 + m] = bv.z;
            Bs[(q + 3) * 68 + m] = bv.w;
        }
    }
    __syncthreads();

    unsigned long long acc[4][2];
#pragma unroll
    for (int i = 0; i < 4; ++i) { acc[i][0] = 0ULL; acc[i][1] = 0ULL; }

#pragma unroll 16
    for (int kk = 0; kk < 64; ++kk) {
        float4 a = *(const float4*)&As[kk * 68 + trow];
        ulonglong2 b2 = *(const ulonglong2*)&Bs[kk * 68 + tcol];
        unsigned long long a0 = pack2(a.x, a.x), a1 = pack2(a.y, a.y);
        unsigned long long a2 = pack2(a.z, a.z), a3 = pack2(a.w, a.w);
        fma2(acc[0][0], a0, b2.x); fma2(acc[0][1], a0, b2.y);
        fma2(acc[1][0], a1, b2.x); fma2(acc[1][1], a1, b2.y);
        fma2(acc[2][0], a2, b2.x); fma2(acc[2][1], a2, b2.y);
        fma2(acc[3][0], a3, b2.x); fma2(acc[3][1], a3, b2.y);
    }

#pragma unroll
    for (int i = 0; i < 4; ++i) {
        int gi = i0 + trow + i;
#pragma unroll
        for (int p = 0; p < 2; ++p) {
            float2 c = unpack2(acc[i][p]);
            int gj = j0 + tcol + 2 * p;
            float2 t = *(const float2*)&td[((size_t)b * Nn + gi) * Nn + gj];
            float2 o = make_float2(c.x * 0.125f - 0.1f * t.x,
                                   c.y * 0.125f - 0.1f * t.y);
            *(float2*)&g_S[((size_t)bh * Nn + gi) * Nn + gj] = o;
        }
    }
}

// ============================================================================
// Fused: per (b,i): exact top-k threshold (4 heads, one warp each),
// masked softmax, adjacency (head mean), sparse attn @ V -> g_M.
// ============================================================================
__global__ void __launch_bounds__(256) fused_attn_kernel(
    const int* __restrict__ topk_ptr, float* __restrict__ out_adj)
{
    __shared__ __align__(16) float sc[4][1024];
    __shared__ __align__(16) float adjs[1024];
    __shared__ __align__(16) float msgs[256];
    __shared__ float redbuf[8];
    __shared__ float s_kth[4];
    __shared__ float s_max[4];
    __shared__ int   s_cnt;
    __shared__ int   jlist[1024];

    const int tid  = threadIdx.x;
    const int bi   = blockIdx.x;
    const int b    = bi >> 10;
    const int i    = bi & 1023;
    const int warp = tid >> 5, lane = tid & 31;

    // load scores for 4 heads (coalesced float4)
#pragma unroll
    for (int h = 0; h < 4; ++h) {
        const float4* src = (const float4*)(g_S + (((size_t)(b * 4 + h) * Nn + i) * Nn));
        ((float4*)sc[h])[tid] = src[tid];
    }
    ((float4*)adjs)[tid] = make_float4(0.f, 0.f, 0.f, 0.f);
    msgs[tid] = 0.f;
    __syncthreads();

    int kv = *topk_ptr;
    if (kv > Nn) kv = Nn;
    if (kv < 1)  kv = 1;

    // ---- exact kth-largest per head: warp h owns head h ----
    if (warp < 4) {
        const float* row = sc[warp];
        unsigned u[32];
        float fm = -3.4e38f;
#pragma unroll
        for (int e = 0; e < 32; ++e) {
            float x = row[e * 32 + lane];
            fm = fmaxf(fm, x);
            u[e] = mapf(x);
        }
#pragma unroll
        for (int o = 16; o; o >>= 1) fm = fmaxf(fm, __shfl_xor_sync(0xffffffffu, fm, o));

        unsigned pref = 0, kthU = 0;
        bool got = false;
        for (int bit = 31; bit >= 0; --bit) {
            unsigned cand = pref | (1u << bit);
            int c = 0;
#pragma unroll
            for (int e = 0; e < 32; ++e) c += (u[e] >= cand) ? 1 : 0;
#pragma unroll
            for (int o = 16; o; o >>= 1) c += __shfl_xor_sync(0xffffffffu, c, o);
            if (c == kv) {
                // exactly k elements >= cand: kth = min of that set
                unsigned mn = 0xFFFFFFFFu;
#pragma unroll
                for (int e = 0; e < 32; ++e)
                    if (u[e] >= cand) mn = umin(mn, u[e]);
#pragma unroll
                for (int o = 16; o; o >>= 1) mn = umin(mn, __shfl_xor_sync(0xffffffffu, mn, o));
                kthU = mn; got = true; break;
            }
            if (c > kv) pref = cand;
        }
        if (!got) kthU = pref;  // ties case: pref is exact kth
        if (lane == 0) { s_kth[warp] = invmap(kthU); s_max[warp] = fm; }
    }
    __syncthreads();

    // ---- per head: masked softmax, adjacency accum, sparse attn@V ----
    for (int h = 0; h < 4; ++h) {
        const float kth = s_kth[h];
        const float mx  = s_max[h];
        float ev[4];
        float lsum = 0.f;
#pragma unroll
        for (int r = 0; r < 4; ++r) {
            float s = sc[h][r * 256 + tid];
            float e = (s >= kth) ? __expf(s - mx) : 0.f;
            ev[r] = e;
            lsum += e;
        }
#pragma unroll
        for (int o = 16; o; o >>= 1) lsum += __shfl_xor_sync(0xffffffffu, lsum, o);
        if (lane == 0) redbuf[warp] = lsum;
        if (tid == 0)  s_cnt = 0;
        __syncthreads();

        float tot = 0.f;
#pragma unroll
        for (int w = 0; w < 8; ++w) tot += redbuf[w];
        float inv = 1.f / tot;  // at least exp(0)=1 survives -> tot >= 1

#pragma unroll
        for (int r = 0; r < 4; ++r) {
            int j = r * 256 + tid;
            float a = ev[r] * inv;
            sc[h][j] = a;
            adjs[j] += 0.25f * a;
            if (a > 0.f) {
                int p = atomicAdd(&s_cnt, 1);
                jlist[p] = j;
            }
        }
        __syncthreads();

        const int cnt  = s_cnt;
        const int d    = tid & 63;
        const int part = tid >> 6;
        const float* vb = g_V + (size_t)b * Nn * 256 + h * 64 + d;
        float acc = 0.f;
        for (int l = part; l < cnt; l += 4) {
            int j = jlist[l];
            acc = fmaf(sc[h][j], __ldg(&vb[(size_t)j * 256]), acc);
        }
        atomicAdd(&msgs[(h << 6) + d], acc);
        __syncthreads();
    }

    // ---- outputs ----
    float* arow = out_adj + ((size_t)(b * Nn) + i) * Nn;
    ((float4*)arow)[tid] = ((const float4*)adjs)[tid];
    g_M[((size_t)(b * Nn) + i) * 256 + tid] = msgs[tid];
}

// ============================================================================
extern "C" void kernel_launch(void* const* d_in, const int* in_sizes, int n_in,
                              void* d_out, int out_size)
{
    const float* h_in = (const float*)d_in[0];
    const float* td   = (const float*)d_in[1];
    const float* Wq   = (const float*)d_in[2];
    const float* bq   = (const float*)d_in[3];
    const float* Wk   = (const float*)d_in[4];
    const float* bk   = (const float*)d_in[5];
    const float* Wv   = (const float*)d_in[6];
    const float* bv   = (const float*)d_in[7];
    const float* Wo   = (const float*)d_in[8];
    const float* bo   = (const float*)d_in[9];
    const int*   tk   = (const int*)d_in[10];

    float* out_adj = (float*)d_out;
    float* out_msg = out_adj + (size_t)Bn * Nn * Nn;

    float *q, *k, *v, *m;
    cudaGetSymbolAddress((void**)&q, g_Q);
    cudaGetSymbolAddress((void**)&k, g_K);
    cudaGetSymbolAddress((void**)&v, g_V);
    cudaGetSymbolAddress((void**)&m, g_M);

    dim3 gp(Dn / 64, ROWS / 64);  // (4, 128)
    gemm256_kernel<<<gp, 256>>>(h_in, Wq, bq, q);
    gemm256_kernel<<<gp, 256>>>(h_in, Wk, bk, k);
    gemm256_kernel<<<gp, 256>>>(h_in, Wv, bv, v);
    scores_kernel<<<dim3(Nn / 64, Nn / 64, Bn * Hn), 256>>>(td);
    fused_attn_kernel<<<ROWS, 256>>>(tk, out_adj);
    gemm256_kernel<<<gp, 256>>>(m, Wo, bo, out_msg);
}

// round 2
// speedup vs baseline: 1.2446x; 1.2446x over previous
#include <cuda_runtime.h>
#include <cstdint>
#include <cstddef>

#define DI __device__ __forceinline__

// Problem shape (fixed for this instance)
constexpr int Bn = 8, Nn = 1024, Dn = 256, Hn = 4;
constexpr int ROWS = Bn * Nn;  // 8192

// -------- scratch (static device globals: allocation-free) --------
__device__ float g_Q[ROWS * Dn];
__device__ float g_K[ROWS * Dn];
__device__ float g_V[ROWS * Dn];
__device__ float g_M[ROWS * Dn];
__device__ float g_S[(size_t)Bn * Hn * Nn * Nn];  // 134 MB score scratch

// -------- packed f32x2 helpers (sm_100+) --------
DI unsigned long long pack2(float lo, float hi) {
    unsigned long long r;
    asm("mov.b64 %0, {%1, %2};" : "=l"(r) : "f"(lo), "f"(hi));
    return r;
}
DI void fma2(unsigned long long& d, unsigned long long a, unsigned long long b) {
    asm("fma.rn.f32x2 %0, %1, %2, %0;" : "+l"(d) : "l"(a), "l"(b));
}
DI float2 unpack2(unsigned long long v) {
    float lo, hi;
    asm("mov.b64 {%0, %1}, %2;" : "=f"(lo), "=f"(hi) : "l"(v));
    return make_float2(lo, hi);
}

// monotone float->uint mapping (order-preserving)
DI unsigned mapf(float x) {
    unsigned b = __float_as_uint(x);
    return (b & 0x80000000u) ? ~b : (b | 0x80000000u);
}
DI float invmap(unsigned u) {
    unsigned b = (u & 0x80000000u) ? (u & 0x7FFFFFFFu) : ~u;
    return __uint_as_float(b);
}

// ============================================================================
// GEMM: C[m,n] = sum_k A[m*256+k] * W[n*256+k] + bias[n]
// M = 8192, N = 256, K = 256. CTA tile 128x128, BK=16, 256 thr, 8x8/thread.
// Thread cols: {c0..c0+3} and {c0+64..c0+67}, c0 = (tid&15)*4.
// ============================================================================
__global__ void __launch_bounds__(256, 2) gemm256_kernel(
    const float* __restrict__ A, const float* __restrict__ W,
    const float* __restrict__ bias, float* __restrict__ C)
{
    __shared__ __align__(16) float As[16][132];
    __shared__ __align__(16) float Bs[16][132];

    const int tid  = threadIdx.x;
    const int m0   = blockIdx.y * 128;
    const int n0   = blockIdx.x * 128;
    const int trow = (tid >> 4) << 3;      // 0..120
    const int c0   = (tid & 15) << 2;      // 0..60

    const int r = tid >> 2;                // 0..63 (load row, +64 on 2nd pass)
    const int q = (tid & 3) << 2;          // 0,4,8,12

    unsigned long long acc[8][4];
#pragma unroll
    for (int i = 0; i < 8; ++i)
#pragma unroll
        for (int p = 0; p < 4; ++p) acc[i][p] = 0ULL;

    for (int kb = 0; kb < 256; kb += 16) {
        __syncthreads();
#pragma unroll
        for (int l = 0; l < 2; ++l) {
            int rr = r + 64 * l;
            float4 av = *(const float4*)(A + (size_t)(m0 + rr) * 256 + kb + q);
            float4 wv = *(const float4*)(W + (size_t)(n0 + rr) * 256 + kb + q);
            As[q + 0][rr] = av.x; As[q + 1][rr] = av.y;
            As[q + 2][rr] = av.z; As[q + 3][rr] = av.w;
            Bs[q + 0][rr] = wv.x; Bs[q + 1][rr] = wv.y;
            Bs[q + 2][rr] = wv.z; Bs[q + 3][rr] = wv.w;
        }
        __syncthreads();
#pragma unroll
        for (int kk = 0; kk < 16; ++kk) {
            float4 a0 = *(const float4*)&As[kk][trow];
            float4 a1 = *(const float4*)&As[kk][trow + 4];
            ulonglong2 b0 = *(const ulonglong2*)&Bs[kk][c0];
            ulonglong2 b1 = *(const ulonglong2*)&Bs[kk][c0 + 64];
            unsigned long long ad[8];
            ad[0] = pack2(a0.x, a0.x); ad[1] = pack2(a0.y, a0.y);
            ad[2] = pack2(a0.z, a0.z); ad[3] = pack2(a0.w, a0.w);
            ad[4] = pack2(a1.x, a1.x); ad[5] = pack2(a1.y, a1.y);
            ad[6] = pack2(a1.z, a1.z); ad[7] = pack2(a1.w, a1.w);
#pragma unroll
            for (int i = 0; i < 8; ++i) {
                fma2(acc[i][0], ad[i], b0.x);
                fma2(acc[i][1], ad[i], b0.y);
                fma2(acc[i][2], ad[i], b1.x);
                fma2(acc[i][3], ad[i], b1.y);
            }
        }
    }

    float4 bb0 = *(const float4*)&bias[n0 + c0];
    float4 bb1 = *(const float4*)&bias[n0 + c0 + 64];
#pragma unroll
    for (int i = 0; i < 8; ++i) {
        int m = m0 + trow + i;
        float2 v0 = unpack2(acc[i][0]), v1 = unpack2(acc[i][1]);
        float2 v2 = unpack2(acc[i][2]), v3 = unpack2(acc[i][3]);
        float4 o0 = make_float4(v0.x + bb0.x, v0.y + bb0.y, v1.x + bb0.z, v1.y + bb0.w);
        float4 o1 = make_float4(v2.x + bb1.x, v2.y + bb1.y, v3.x + bb1.z, v3.y + bb1.w);
        *(float4*)&C[(size_t)m * 256 + n0 + c0]      = o0;
        *(float4*)&C[(size_t)m * 256 + n0 + c0 + 64] = o1;
    }
}

// ============================================================================
// Scores: S[b,h,i,j] = 0.125 * dot(Q[b,i,h*64:+64], K[b,j,h*64:+64]) - 0.1*td[b,i,j]
// CTA tile 128x128, K=64 in 4 chunks of 16, 256 thr, 8x8/thread.
// ============================================================================
__global__ void __launch_bounds__(256, 2) scores_kernel(const float* __restrict__ td)
{
    __shared__ __align__(16) float As[16][132];
    __shared__ __align__(16) float Bs[16][132];

    const int tid  = threadIdx.x;
    const int bh   = blockIdx.z;        // b*4 + h
    const int b    = bh >> 2;
    const int h    = bh & 3;
    const int i0   = blockIdx.y * 128;
    const int j0   = blockIdx.x * 128;
    const int trow = (tid >> 4) << 3;
    const int c0   = (tid & 15) << 2;

    const int r = tid >> 2;
    const int q = (tid & 3) << 2;

    const float* Qb = g_Q + ((size_t)(b * Nn) + i0) * 256 + h * 64;
    const float* Kb = g_K + ((size_t)(b * Nn) + j0) * 256 + h * 64;

    unsigned long long acc[8][4];
#pragma unroll
    for (int i = 0; i < 8; ++i)
#pragma unroll
        for (int p = 0; p < 4; ++p) acc[i][p] = 0ULL;

    for (int kb = 0; kb < 64; kb += 16) {
        __syncthreads();
#pragma unroll
        for (int l = 0; l < 2; ++l) {
            int rr = r + 64 * l;
            float4 av = *(const float4*)(Qb + (size_t)rr * 256 + kb + q);
            float4 bv = *(const float4*)(Kb + (size_t)rr * 256 + kb + q);
            As[q + 0][rr] = av.x; As[q + 1][rr] = av.y;
            As[q + 2][rr] = av.z; As[q + 3][rr] = av.w;
            Bs[q + 0][rr] = bv.x; Bs[q + 1][rr] = bv.y;
            Bs[q + 2][rr] = bv.z; Bs[q + 3][rr] = bv.w;
        }
        __syncthreads();
#pragma unroll
        for (int kk = 0; kk < 16; ++kk) {
            float4 a0 = *(const float4*)&As[kk][trow];
            float4 a1 = *(const float4*)&As[kk][trow + 4];
            ulonglong2 b0 = *(const ulonglong2*)&Bs[kk][c0];
            ulonglong2 b1 = *(const ulonglong2*)&Bs[kk][c0 + 64];
            unsigned long long ad[8];
            ad[0] = pack2(a0.x, a0.x); ad[1] = pack2(a0.y, a0.y);
            ad[2] = pack2(a0.z, a0.z); ad[3] = pack2(a0.w, a0.w);
            ad[4] = pack2(a1.x, a1.x); ad[5] = pack2(a1.y, a1.y);
            ad[6] = pack2(a1.z, a1.z); ad[7] = pack2(a1.w, a1.w);
#pragma unroll
            for (int i = 0; i < 8; ++i) {
                fma2(acc[i][0], ad[i], b0.x);
                fma2(acc[i][1], ad[i], b0.y);
                fma2(acc[i][2], ad[i], b1.x);
                fma2(acc[i][3], ad[i], b1.y);
            }
        }
    }

#pragma unroll
    for (int i = 0; i < 8; ++i) {
        int gi = i0 + trow + i;
        const float* tdr = td + ((size_t)b * Nn + gi) * Nn + j0;
        float* Sr = g_S + ((size_t)bh * Nn + gi) * Nn + j0;
        float4 t0 = *(const float4*)&tdr[c0];
        float4 t1 = *(const float4*)&tdr[c0 + 64];
        float2 v0 = unpack2(acc[i][0]), v1 = unpack2(acc[i][1]);
        float2 v2 = unpack2(acc[i][2]), v3 = unpack2(acc[i][3]);
        float4 o0 = make_float4(v0.x * 0.125f - 0.1f * t0.x,
                                v0.y * 0.125f - 0.1f * t0.y,
                                v1.x * 0.125f - 0.1f * t0.z,
                                v1.y * 0.125f - 0.1f * t0.w);
        float4 o1 = make_float4(v2.x * 0.125f - 0.1f * t1.x,
                                v2.y * 0.125f - 0.1f * t1.y,
                                v3.x * 0.125f - 0.1f * t1.z,
                                v3.y * 0.125f - 0.1f * t1.w);
        *(float4*)&Sr[c0]      = o0;
        *(float4*)&Sr[c0 + 64] = o1;
    }
}

// ============================================================================
// Fused: per (b,i): exact top-k threshold (4 heads, one warp each),
// masked softmax, adjacency (head mean), sparse attn @ V -> g_M.
// ============================================================================
__global__ void __launch_bounds__(256) fused_attn_kernel(
    const int* __restrict__ topk_ptr, float* __restrict__ out_adj)
{
    __shared__ __align__(16) float sc[4][1024];
    __shared__ __align__(16) float adjs[1024];
    __shared__ __align__(16) float msgs[256];
    __shared__ float redbuf[8];
    __shared__ float s_kth[4];
    __shared__ float s_max[4];
    __shared__ int   s_cnt;
    __shared__ int   jlist[1024];

    const int tid  = threadIdx.x;
    const int bi   = blockIdx.x;
    const int b    = bi >> 10;
    const int i    = bi & 1023;
    const int warp = tid >> 5, lane = tid & 31;

    // load scores for 4 heads (coalesced float4)
#pragma unroll
    for (int h = 0; h < 4; ++h) {
        const float4* src = (const float4*)(g_S + (((size_t)(b * 4 + h) * Nn + i) * Nn));
        ((float4*)sc[h])[tid] = src[tid];
    }
    ((float4*)adjs)[tid] = make_float4(0.f, 0.f, 0.f, 0.f);
    msgs[tid] = 0.f;
    __syncthreads();

    int kv = *topk_ptr;
    if (kv > Nn) kv = Nn;
    if (kv < 1)  kv = 1;

    // ---- exact kth-largest per head: warp h owns head h ----
    if (warp < 4) {
        const float* row = sc[warp];
        unsigned u[32];
        float fm = -3.4e38f;
#pragma unroll
        for (int e = 0; e < 32; ++e) {
            float x = row[e * 32 + lane];
            fm = fmaxf(fm, x);
            u[e] = mapf(x);
        }
#pragma unroll
        for (int o = 16; o; o >>= 1) fm = fmaxf(fm, __shfl_xor_sync(0xffffffffu, fm, o));

        unsigned pref = 0, kthU = 0;
        bool got = false;
        for (int bit = 31; bit >= 0; --bit) {
            unsigned cand = pref | (1u << bit);
            int c = 0;
#pragma unroll
            for (int e = 0; e < 32; ++e) c += (u[e] >= cand) ? 1 : 0;
#pragma unroll
            for (int o = 16; o; o >>= 1) c += __shfl_xor_sync(0xffffffffu, c, o);
            if (c == kv) {
                // exactly k elements >= cand: kth = min of that set
                unsigned mn = 0xFFFFFFFFu;
#pragma unroll
                for (int e = 0; e < 32; ++e)
                    if (u[e] >= cand) mn = umin(mn, u[e]);
#pragma unroll
                for (int o = 16; o; o >>= 1) mn = umin(mn, __shfl_xor_sync(0xffffffffu, mn, o));
                kthU = mn; got = true; break;
            }
            if (c > kv) pref = cand;
        }
        if (!got) kthU = pref;  // ties case: pref is exact kth
        if (lane == 0) { s_kth[warp] = invmap(kthU); s_max[warp] = fm; }
    }
    __syncthreads();

    // ---- per head: masked softmax, adjacency accum, sparse attn@V ----
    for (int h = 0; h < 4; ++h) {
        const float kth = s_kth[h];
        const float mx  = s_max[h];
        float ev[4];
        float lsum = 0.f;
#pragma unroll
        for (int r = 0; r < 4; ++r) {
            float s = sc[h][r * 256 + tid];
            float e = (s >= kth) ? __expf(s - mx) : 0.f;
            ev[r] = e;
            lsum += e;
        }
#pragma unroll
        for (int o = 16; o; o >>= 1) lsum += __shfl_xor_sync(0xffffffffu, lsum, o);
        if (lane == 0) redbuf[warp] = lsum;
        if (tid == 0)  s_cnt = 0;
        __syncthreads();

        float tot = 0.f;
#pragma unroll
        for (int w = 0; w < 8; ++w) tot += redbuf[w];
        float inv = 1.f / tot;  // at least exp(0)=1 survives -> tot >= 1

#pragma unroll
        for (int r = 0; r < 4; ++r) {
            int j = r * 256 + tid;
            float a = ev[r] * inv;
            sc[h][j] = a;
            adjs[j] += 0.25f * a;
            if (a > 0.f) {
                int p = atomicAdd(&s_cnt, 1);
                jlist[p] = j;
            }
        }
        __syncthreads();

        const int cnt  = s_cnt;
        const int d    = tid & 63;
        const int part = tid >> 6;
        const float* vb = g_V + (size_t)b * Nn * 256 + h * 64 + d;
        float acc = 0.f;
        for (int l = part; l < cnt; l += 4) {
            int j = jlist[l];
            acc = fmaf(sc[h][j], __ldg(&vb[(size_t)j * 256]), acc);
        }
        atomicAdd(&msgs[(h << 6) + d], acc);
        __syncthreads();
    }

    // ---- outputs ----
    float* arow = out_adj + ((size_t)(b * Nn) + i) * Nn;
    ((float4*)arow)[tid] = ((const float4*)adjs)[tid];
    g_M[((size_t)(b * Nn) + i) * 256 + tid] = msgs[tid];
}

// ============================================================================
extern "C" void kernel_launch(void* const* d_in, const int* in_sizes, int n_in,
                              void* d_out, int out_size)
{
    const float* h_in = (const float*)d_in[0];
    const float* td   = (const float*)d_in[1];
    const float* Wq   = (const float*)d_in[2];
    const float* bq   = (const float*)d_in[3];
    const float* Wk   = (const float*)d_in[4];
    const float* bk   = (const float*)d_in[5];
    const float* Wv   = (const float*)d_in[6];
    const float* bv   = (const float*)d_in[7];
    const float* Wo   = (const float*)d_in[8];
    const float* bo   = (const float*)d_in[9];
    const int*   tk   = (const int*)d_in[10];

    float* out_adj = (float*)d_out;
    float* out_msg = out_adj + (size_t)Bn * Nn * Nn;

    float *q, *k, *v, *m;
    cudaGetSymbolAddress((void**)&q, g_Q);
    cudaGetSymbolAddress((void**)&k, g_K);
    cudaGetSymbolAddress((void**)&v, g_V);
    cudaGetSymbolAddress((void**)&m, g_M);

    dim3 gp(Dn / 128, ROWS / 128);  // (2, 64)
    gemm256_kernel<<<gp, 256>>>(h_in, Wq, bq, q);
    gemm256_kernel<<<gp, 256>>>(h_in, Wk, bk, k);
    gemm256_kernel<<<gp, 256>>>(h_in, Wv, bv, v);
    scores_kernel<<<dim3(Nn / 128, Nn / 128, Bn * Hn), 256>>>(td);
    fused_attn_kernel<<<ROWS, 256>>>(tk, out_adj);
    gemm256_kernel<<<gp, 256>>>(m, Wo, bo, out_msg);
}